// round 3
// baseline (speedup 1.0000x reference)
#include <cuda_runtime.h>
#include <cuda_bf16.h>

// EntNet forward, dead-code-eliminated:
//  - candidate memory (U,V,W, prelu a_mem) is dead in the reference
//  - gate (1+sigmoid(...)) cancels under per-column L2 normalization,
//    so F_i@input, keys, and the sigmoid are dead too.
// Live: s_q = F_q@query; mhat_j = mn_j/||mn_j||; p = softmax(s_q . mhat);
//       u = mhat @ p; y = R @ prelu(s_q + H@u, a_out)

#define D 4096
#define M 1024
#define L 8192
#define SPLITS 32           // D split for column-stat pass
#define ROWS_PER 128        // D / SPLITS

__device__ float g_sq[D];
__device__ float g_u[D];
__device__ float g_v[D];
__device__ float g_c[M];
__device__ float g_pdot[SPLITS * M];
__device__ float g_pss[SPLITS * M];

__device__ __forceinline__ float warp_reduce_sum(float v) {
#pragma unroll
    for (int o = 16; o > 0; o >>= 1) v += __shfl_down_sync(0xFFFFFFFFu, v, o);
    return v;
}

__device__ __forceinline__ float dot4(float4 a, float4 b) {
    return a.x * b.x + a.y * b.y + a.z * b.z + a.w * b.w;
}

// ---------------------------------------------------------------------------
// K1: s_q[d] = dot(F_q[d,:], query)   (4096 rows x 8192 cols)
// warp-per-row, query staged in shared, 4 independent load/acc streams
// ---------------------------------------------------------------------------
__global__ __launch_bounds__(256) void k_sq(const float* __restrict__ F,
                                            const float* __restrict__ q) {
    __shared__ float4 shq[L / 4];
    for (int i = threadIdx.x; i < L / 4; i += 256)
        shq[i] = reinterpret_cast<const float4*>(q)[i];
    __syncthreads();

    int warp = threadIdx.x >> 5, lane = threadIdx.x & 31;
    int row = blockIdx.x * 8 + warp;
    const float4* Fr = reinterpret_cast<const float4*>(F + (size_t)row * L);
    float a0 = 0.f, a1 = 0.f, a2 = 0.f, a3 = 0.f;
#pragma unroll 4
    for (int i = lane; i < L / 4; i += 128) {
        float4 f0 = Fr[i];
        float4 f1 = Fr[i + 32];
        float4 f2 = Fr[i + 64];
        float4 f3 = Fr[i + 96];
        a0 += dot4(f0, shq[i]);
        a1 += dot4(f1, shq[i + 32]);
        a2 += dot4(f2, shq[i + 64]);
        a3 += dot4(f3, shq[i + 96]);
    }
    float acc = warp_reduce_sum((a0 + a1) + (a2 + a3));
    if (lane == 0) g_sq[row] = acc;
}

// ---------------------------------------------------------------------------
// K2: per-column partial dot(s_q, mn[:,j]) and sum-of-squares over a D-slice.
// thread = column j (coalesced along row), blockIdx.y = D-slice.
// ---------------------------------------------------------------------------
__global__ __launch_bounds__(256) void k_colpart(const float* __restrict__ mn) {
    int j = blockIdx.x * 256 + threadIdx.x;   // 4 x-blocks cover M=1024
    int s = blockIdx.y;                       // 32 slices of 128 rows
    __shared__ float shq[ROWS_PER];
    if (threadIdx.x < ROWS_PER) shq[threadIdx.x] = g_sq[s * ROWS_PER + threadIdx.x];
    __syncthreads();

    const float* base = mn + (size_t)s * ROWS_PER * M + j;
    float d0 = 0.f, d1 = 0.f, s0 = 0.f, s1 = 0.f;
#pragma unroll 8
    for (int d = 0; d < ROWS_PER; d += 2) {
        float v0 = base[(size_t)d * M];
        float v1 = base[(size_t)(d + 1) * M];
        d0 += v0 * shq[d];
        d1 += v1 * shq[d + 1];
        s0 += v0 * v0;
        s1 += v1 * v1;
    }
    g_pdot[s * M + j] = d0 + d1;
    g_pss [s * M + j] = s0 + s1;
}

// ---------------------------------------------------------------------------
// K3: reduce partials, softmax over M, fold 1/norm into c_j = p_j / ||mn_j||.
// Single block of 1024 threads (deterministic, no atomics).
// ---------------------------------------------------------------------------
__global__ __launch_bounds__(1024) void k_softmax() {
    int j = threadIdx.x;
    float dot = 0.f, ss = 0.f;
#pragma unroll
    for (int s = 0; s < SPLITS; ++s) {
        dot += g_pdot[s * M + j];
        ss  += g_pss [s * M + j];
    }
    float norm = fmaxf(sqrtf(ss), 1e-12f);
    float t = dot / norm;

    __shared__ float red[32];
    __shared__ float bcast;
    int lane = j & 31, wid = j >> 5;

    // block max
    float m = t;
#pragma unroll
    for (int o = 16; o > 0; o >>= 1) m = fmaxf(m, __shfl_down_sync(0xFFFFFFFFu, m, o));
    if (lane == 0) red[wid] = m;
    __syncthreads();
    if (wid == 0) {
        float x = red[lane];
#pragma unroll
        for (int o = 16; o > 0; o >>= 1) x = fmaxf(x, __shfl_down_sync(0xFFFFFFFFu, x, o));
        if (lane == 0) bcast = x;
    }
    __syncthreads();
    float tmax = bcast;

    float e = expf(t - tmax);

    // block sum
    float su = warp_reduce_sum(e);
    __syncthreads();
    if (lane == 0) red[wid] = su;
    __syncthreads();
    if (wid == 0) {
        float x = red[lane];
        x = warp_reduce_sum(x);
        if (lane == 0) bcast = x;
    }
    __syncthreads();
    float esum = bcast;

    g_c[j] = e / (esum * norm);
}

// ---------------------------------------------------------------------------
// K4: u[d] = dot(mn[d,:], c)   (4096 rows x 1024 cols), warp-per-row
// no staging sync; c (4KB) hits L1/L2, mn should be L2-resident
// ---------------------------------------------------------------------------
__global__ __launch_bounds__(256) void k_u(const float* __restrict__ mn) {
    int warp = threadIdx.x >> 5, lane = threadIdx.x & 31;
    int row = blockIdx.x * 8 + warp;
    const float4* r  = reinterpret_cast<const float4*>(mn + (size_t)row * M);
    const float4* c4 = reinterpret_cast<const float4*>(g_c);
    float a0 = 0.f, a1 = 0.f;
#pragma unroll
    for (int k = 0; k < 8; k += 2) {
        float4 m0 = r[lane + k * 32];
        float4 m1 = r[lane + (k + 1) * 32];
        a0 += dot4(m0, __ldg(&c4[lane + k * 32]));
        a1 += dot4(m1, __ldg(&c4[lane + (k + 1) * 32]));
    }
    float acc = warp_reduce_sum(a0 + a1);
    if (lane == 0) g_u[row] = acc;
}

// ---------------------------------------------------------------------------
// K5: v[d] = prelu(s_q[d] + dot(H[d,:], u), a_out)   (4096x4096)
// ---------------------------------------------------------------------------
__global__ __launch_bounds__(256) void k_v(const float* __restrict__ H,
                                           const float* __restrict__ a_out) {
    __shared__ float4 shu[D / 4];
    for (int i = threadIdx.x; i < D / 4; i += 256)
        shu[i] = reinterpret_cast<const float4*>(g_u)[i];
    __syncthreads();

    int warp = threadIdx.x >> 5, lane = threadIdx.x & 31;
    int row = blockIdx.x * 8 + warp;
    const float4* Hr = reinterpret_cast<const float4*>(H + (size_t)row * D);
    float a0 = 0.f, a1 = 0.f, a2 = 0.f, a3 = 0.f;
#pragma unroll 2
    for (int i = lane; i < D / 4; i += 128) {
        float4 f0 = Hr[i];
        float4 f1 = Hr[i + 32];
        float4 f2 = Hr[i + 64];
        float4 f3 = Hr[i + 96];
        a0 += dot4(f0, shu[i]);
        a1 += dot4(f1, shu[i + 32]);
        a2 += dot4(f2, shu[i + 64]);
        a3 += dot4(f3, shu[i + 96]);
    }
    float acc = warp_reduce_sum((a0 + a1) + (a2 + a3));
    if (lane == 0) {
        float x = g_sq[row] + acc;
        float a = a_out[0];
        g_v[row] = (x >= 0.f) ? x : a * x;
    }
}

// ---------------------------------------------------------------------------
// K6: y[d] = dot(R[d,:], v)   (4096x4096) -> d_out
// ---------------------------------------------------------------------------
__global__ __launch_bounds__(256) void k_y(const float* __restrict__ R,
                                           float* __restrict__ out) {
    __shared__ float4 shv[D / 4];
    for (int i = threadIdx.x; i < D / 4; i += 256)
        shv[i] = reinterpret_cast<const float4*>(g_v)[i];
    __syncthreads();

    int warp = threadIdx.x >> 5, lane = threadIdx.x & 31;
    int row = blockIdx.x * 8 + warp;
    const float4* Rr = reinterpret_cast<const float4*>(R + (size_t)row * D);
    float a0 = 0.f, a1 = 0.f, a2 = 0.f, a3 = 0.f;
#pragma unroll 2
    for (int i = lane; i < D / 4; i += 128) {
        float4 f0 = Rr[i];
        float4 f1 = Rr[i + 32];
        float4 f2 = Rr[i + 64];
        float4 f3 = Rr[i + 96];
        a0 += dot4(f0, shv[i]);
        a1 += dot4(f1, shv[i + 32]);
        a2 += dot4(f2, shv[i + 64]);
        a3 += dot4(f3, shv[i + 96]);
    }
    float acc = warp_reduce_sum((a0 + a1) + (a2 + a3));
    if (lane == 0) out[row] = acc;
}

extern "C" void kernel_launch(void* const* d_in, const int* in_sizes, int n_in,
                              void* d_out, int out_size) {
    // metadata order: input, query, F_i, F_q, keys, memory_nodes, U, V, W, R, H, a_mem, a_out
    const float* query = (const float*)d_in[1];
    const float* F_q   = (const float*)d_in[3];
    const float* mn    = (const float*)d_in[5];
    const float* Rm    = (const float*)d_in[9];
    const float* Hm    = (const float*)d_in[10];
    const float* a_out = (const float*)d_in[12];
    float* out = (float*)d_out;

    k_sq<<<D / 8, 256>>>(F_q, query);
    dim3 g2(M / 256, SPLITS);
    k_colpart<<<g2, 256>>>(mn);
    k_softmax<<<1, 1024>>>();
    k_u<<<D / 8, 256>>>(mn);
    k_v<<<D / 8, 256>>>(Hm, a_out);
    k_y<<<D / 8, 256>>>(Rm, out);
}

// round 4
// speedup vs baseline: 1.1449x; 1.1449x over previous
#include <cuda_runtime.h>
#include <cuda_bf16.h>

// EntNet forward, dead-code-eliminated:
//  - candidate memory (U,V,W, prelu a_mem) is dead in the reference
//  - gate (1+sigmoid(...)) cancels under per-column L2 normalization,
//    so F_i@input, keys, and the sigmoid are dead too.
// Live: s_q = F_q@query; mhat_j = mn_j/||mn_j||; p = softmax(s_q . mhat);
//       u = mhat @ p; y = R @ prelu(s_q + H@u, a_out)

#define D 4096
#define M 1024
#define L 8192
#define SPLITS 32
#define ROWS_PER 128        // D / SPLITS

__device__ float g_sq[D];
__device__ float g_u[D];
__device__ float g_v[D];
__device__ float g_c[M];
__device__ float g_pdot[SPLITS * M];
__device__ float g_pss[SPLITS * M];

__device__ __forceinline__ float warp_reduce_sum(float v) {
#pragma unroll
    for (int o = 16; o > 0; o >>= 1) v += __shfl_down_sync(0xFFFFFFFFu, v, o);
    return v;
}

__device__ __forceinline__ float dot4(float4 a, float4 b) {
    return a.x * b.x + a.y * b.y + a.z * b.z + a.w * b.w;
}

// block reduce over 256 threads (8 warps)
__device__ __forceinline__ float block_reduce_256(float v) {
    __shared__ float sh[8];
    int lane = threadIdx.x & 31, wid = threadIdx.x >> 5;
    v = warp_reduce_sum(v);
    if (lane == 0) sh[wid] = v;
    __syncthreads();
    if (wid == 0) {
        float x = (lane < 8) ? sh[lane] : 0.f;
#pragma unroll
        for (int o = 4; o > 0; o >>= 1) x += __shfl_down_sync(0xFFFFFFFFu, x, o);
        return x;   // valid in lane 0
    }
    return 0.f;
}

// ---------------------------------------------------------------------------
// K1: s_q[d] = dot(F_q[d,:], query)  — block-per-row, 256 thr, 8 float4/thr
// ---------------------------------------------------------------------------
__global__ __launch_bounds__(256) void k_sq(const float* __restrict__ F,
                                            const float* __restrict__ q) {
    int row = blockIdx.x;
    const float4* Fr = reinterpret_cast<const float4*>(F + (size_t)row * L);
    const float4* q4 = reinterpret_cast<const float4*>(q);
    int t = threadIdx.x;
    float a0 = 0.f, a1 = 0.f, a2 = 0.f, a3 = 0.f;
    // 2048 float4 per row / 256 threads = 8 each; batch loads for MLP
    float4 f0 = Fr[t];           float4 f1 = Fr[t + 256];
    float4 f2 = Fr[t + 512];     float4 f3 = Fr[t + 768];
    float4 f4 = Fr[t + 1024];    float4 f5 = Fr[t + 1280];
    float4 f6 = Fr[t + 1536];    float4 f7 = Fr[t + 1792];
    a0 += dot4(f0, __ldg(&q4[t]));        a1 += dot4(f1, __ldg(&q4[t + 256]));
    a2 += dot4(f2, __ldg(&q4[t + 512]));  a3 += dot4(f3, __ldg(&q4[t + 768]));
    a0 += dot4(f4, __ldg(&q4[t + 1024])); a1 += dot4(f5, __ldg(&q4[t + 1280]));
    a2 += dot4(f6, __ldg(&q4[t + 1536])); a3 += dot4(f7, __ldg(&q4[t + 1792]));
    float acc = block_reduce_256((a0 + a1) + (a2 + a3));
    if (threadIdx.x == 0) g_sq[row] = acc;
}

// ---------------------------------------------------------------------------
// K2: per-column partial dot(s_q, mn[:,j]) and sum-of-squares over a D-slice.
// ---------------------------------------------------------------------------
__global__ __launch_bounds__(256) void k_colpart(const float* __restrict__ mn) {
    int j = blockIdx.x * 256 + threadIdx.x;   // 4 x-blocks cover M=1024
    int s = blockIdx.y;                       // 32 slices of 128 rows
    __shared__ float shq[ROWS_PER];
    if (threadIdx.x < ROWS_PER) shq[threadIdx.x] = g_sq[s * ROWS_PER + threadIdx.x];
    __syncthreads();

    const float* base = mn + (size_t)s * ROWS_PER * M + j;
    float d0 = 0.f, d1 = 0.f, s0 = 0.f, s1 = 0.f;
#pragma unroll 8
    for (int d = 0; d < ROWS_PER; d += 2) {
        float v0 = base[(size_t)d * M];
        float v1 = base[(size_t)(d + 1) * M];
        d0 += v0 * shq[d];
        d1 += v1 * shq[d + 1];
        s0 += v0 * v0;
        s1 += v1 * v1;
    }
    g_pdot[s * M + j] = d0 + d1;
    g_pss [s * M + j] = s0 + s1;
}

// ---------------------------------------------------------------------------
// K3: reduce partials, softmax over M, fold 1/norm into c_j = p_j / ||mn_j||.
// ---------------------------------------------------------------------------
__global__ __launch_bounds__(1024) void k_softmax() {
    int j = threadIdx.x;
    float dot = 0.f, ss = 0.f;
#pragma unroll
    for (int s = 0; s < SPLITS; ++s) {
        dot += g_pdot[s * M + j];
        ss  += g_pss [s * M + j];
    }
    float norm = fmaxf(sqrtf(ss), 1e-12f);
    float t = dot / norm;

    __shared__ float red[32];
    __shared__ float bcast;
    int lane = j & 31, wid = j >> 5;

    float m = t;
#pragma unroll
    for (int o = 16; o > 0; o >>= 1) m = fmaxf(m, __shfl_down_sync(0xFFFFFFFFu, m, o));
    if (lane == 0) red[wid] = m;
    __syncthreads();
    if (wid == 0) {
        float x = red[lane];
#pragma unroll
        for (int o = 16; o > 0; o >>= 1) x = fmaxf(x, __shfl_down_sync(0xFFFFFFFFu, x, o));
        if (lane == 0) bcast = x;
    }
    __syncthreads();
    float tmax = bcast;

    float e = expf(t - tmax);

    float su = warp_reduce_sum(e);
    __syncthreads();
    if (lane == 0) red[wid] = su;
    __syncthreads();
    if (wid == 0) {
        float x = red[lane];
        x = warp_reduce_sum(x);
        if (lane == 0) bcast = x;
    }
    __syncthreads();
    float esum = bcast;

    g_c[j] = e / (esum * norm);
}

// ---------------------------------------------------------------------------
// K4: u[d] = dot(mn[d,:], c) — block-per-row, 256 thr, 1 float4/thr
// mn L2-resident after k_colpart; win = raw thread concurrency
// ---------------------------------------------------------------------------
__global__ __launch_bounds__(256) void k_u(const float* __restrict__ mn) {
    int row = blockIdx.x;
    const float4* r  = reinterpret_cast<const float4*>(mn + (size_t)row * M);
    const float4* c4 = reinterpret_cast<const float4*>(g_c);
    int t = threadIdx.x;
    float acc = dot4(r[t], __ldg(&c4[t]));
    acc = block_reduce_256(acc);
    if (threadIdx.x == 0) g_u[row] = acc;
}

// ---------------------------------------------------------------------------
// K5: v[d] = prelu(s_q[d] + dot(H[d,:], u), a_out) — block-per-row, 4 f4/thr
// ---------------------------------------------------------------------------
__global__ __launch_bounds__(256) void k_v(const float* __restrict__ H,
                                           const float* __restrict__ a_out) {
    int row = blockIdx.x;
    const float4* Hr = reinterpret_cast<const float4*>(H + (size_t)row * D);
    const float4* u4 = reinterpret_cast<const float4*>(g_u);
    int t = threadIdx.x;
    float4 f0 = Hr[t];        float4 f1 = Hr[t + 256];
    float4 f2 = Hr[t + 512];  float4 f3 = Hr[t + 768];
    float a0 = dot4(f0, __ldg(&u4[t]));
    float a1 = dot4(f1, __ldg(&u4[t + 256]));
    float a2 = dot4(f2, __ldg(&u4[t + 512]));
    float a3 = dot4(f3, __ldg(&u4[t + 768]));
    float acc = block_reduce_256((a0 + a1) + (a2 + a3));
    if (threadIdx.x == 0) {
        float x = g_sq[row] + acc;
        float a = a_out[0];
        g_v[row] = (x >= 0.f) ? x : a * x;
    }
}

// ---------------------------------------------------------------------------
// K6: y[d] = dot(R[d,:], v) — block-per-row, 4 f4/thr -> d_out
// ---------------------------------------------------------------------------
__global__ __launch_bounds__(256) void k_y(const float* __restrict__ R,
                                           float* __restrict__ out) {
    int row = blockIdx.x;
    const float4* Rr = reinterpret_cast<const float4*>(R + (size_t)row * D);
    const float4* v4 = reinterpret_cast<const float4*>(g_v);
    int t = threadIdx.x;
    float4 f0 = Rr[t];        float4 f1 = Rr[t + 256];
    float4 f2 = Rr[t + 512];  float4 f3 = Rr[t + 768];
    float a0 = dot4(f0, __ldg(&v4[t]));
    float a1 = dot4(f1, __ldg(&v4[t + 256]));
    float a2 = dot4(f2, __ldg(&v4[t + 512]));
    float a3 = dot4(f3, __ldg(&v4[t + 768]));
    float acc = block_reduce_256((a0 + a1) + (a2 + a3));
    if (threadIdx.x == 0) out[row] = acc;
}

extern "C" void kernel_launch(void* const* d_in, const int* in_sizes, int n_in,
                              void* d_out, int out_size) {
    // metadata order: input, query, F_i, F_q, keys, memory_nodes, U, V, W, R, H, a_mem, a_out
    const float* query = (const float*)d_in[1];
    const float* F_q   = (const float*)d_in[3];
    const float* mn    = (const float*)d_in[5];
    const float* Rm    = (const float*)d_in[9];
    const float* Hm    = (const float*)d_in[10];
    const float* a_out = (const float*)d_in[12];
    float* out = (float*)d_out;

    k_sq<<<D, 256>>>(F_q, query);
    dim3 g2(M / 256, SPLITS);
    k_colpart<<<g2, 256>>>(mn);
    k_softmax<<<1, 1024>>>();
    k_u<<<D, 256>>>(mn);
    k_v<<<D, 256>>>(Hm, a_out);
    k_y<<<D, 256>>>(Rm, out);
}

// round 5
// speedup vs baseline: 1.1867x; 1.0366x over previous
#include <cuda_runtime.h>
#include <cuda_bf16.h>

// EntNet forward, dead-code-eliminated:
//  - candidate memory (U,V,W, prelu a_mem) is dead in the reference
//  - gate (1+sigmoid(...)) cancels under per-column L2 normalization,
//    so F_i@input, keys, and the sigmoid are dead too.
// Live: s_q = F_q@query; mhat_j = mn_j/||mn_j||; p = softmax(s_q . mhat);
//       u = mhat @ p; y = R @ prelu(s_q + H@u, a_out)

#define D 4096
#define M 1024
#define L 8192
#define SPLITS 32
#define ROWS_PER 128        // D / SPLITS

__device__ float g_sq[D];
__device__ float g_u[D];
__device__ float g_v[D];
__device__ float g_c[M];
__device__ float g_pdot[SPLITS * M];
__device__ float g_pss[SPLITS * M];

__device__ __forceinline__ float warp_reduce_sum(float v) {
#pragma unroll
    for (int o = 16; o > 0; o >>= 1) v += __shfl_down_sync(0xFFFFFFFFu, v, o);
    return v;
}

__device__ __forceinline__ float dot4(float4 a, float4 b) {
    return a.x * b.x + a.y * b.y + a.z * b.z + a.w * b.w;
}

__device__ __forceinline__ float4 ldcs4(const float4* p) {
    return __ldcs(p);
}

// ---------------------------------------------------------------------------
// K1: s_q[d] = dot(F_q[d,:], query)  — warp-per-row, no block barriers
// 64 float4/lane, streaming loads on F, L1-cached vector loads
// ---------------------------------------------------------------------------
__global__ __launch_bounds__(256) void k_sq(const float* __restrict__ F,
                                            const float* __restrict__ q) {
    int warp = threadIdx.x >> 5, lane = threadIdx.x & 31;
    int row = blockIdx.x * 8 + warp;
    const float4* Fr = reinterpret_cast<const float4*>(F + (size_t)row * L);
    const float4* q4 = reinterpret_cast<const float4*>(q);
    float a0 = 0.f, a1 = 0.f, a2 = 0.f, a3 = 0.f;
#pragma unroll 4
    for (int k = 0; k < 64; k += 4) {
        int i0 = lane + (k + 0) * 32;
        int i1 = lane + (k + 1) * 32;
        int i2 = lane + (k + 2) * 32;
        int i3 = lane + (k + 3) * 32;
        float4 f0 = ldcs4(&Fr[i0]);
        float4 f1 = ldcs4(&Fr[i1]);
        float4 f2 = ldcs4(&Fr[i2]);
        float4 f3 = ldcs4(&Fr[i3]);
        a0 += dot4(f0, __ldg(&q4[i0]));
        a1 += dot4(f1, __ldg(&q4[i1]));
        a2 += dot4(f2, __ldg(&q4[i2]));
        a3 += dot4(f3, __ldg(&q4[i3]));
    }
    float acc = warp_reduce_sum((a0 + a1) + (a2 + a3));
    if (lane == 0) g_sq[row] = acc;
}

// ---------------------------------------------------------------------------
// K2: per-column partial dot(s_q, mn[:,j]) and sum-of-squares over a D-slice.
// thread = column j (coalesced along row), blockIdx.y = D-slice.
// default caching: warms L2 with mn for k_u.
// ---------------------------------------------------------------------------
__global__ __launch_bounds__(256) void k_colpart(const float* __restrict__ mn) {
    int j = blockIdx.x * 256 + threadIdx.x;   // 4 x-blocks cover M=1024
    int s = blockIdx.y;                       // 32 slices of 128 rows
    __shared__ float shq[ROWS_PER];
    if (threadIdx.x < ROWS_PER) shq[threadIdx.x] = g_sq[s * ROWS_PER + threadIdx.x];
    __syncthreads();

    const float* base = mn + (size_t)s * ROWS_PER * M + j;
    float d0 = 0.f, d1 = 0.f, s0 = 0.f, s1 = 0.f;
#pragma unroll 8
    for (int d = 0; d < ROWS_PER; d += 2) {
        float v0 = base[(size_t)d * M];
        float v1 = base[(size_t)(d + 1) * M];
        d0 += v0 * shq[d];
        d1 += v1 * shq[d + 1];
        s0 += v0 * v0;
        s1 += v1 * v1;
    }
    g_pdot[s * M + j] = d0 + d1;
    g_pss [s * M + j] = s0 + s1;
}

// ---------------------------------------------------------------------------
// K3: reduce partials, softmax over M, fold 1/norm into c_j = p_j / ||mn_j||.
// ---------------------------------------------------------------------------
__global__ __launch_bounds__(1024) void k_softmax() {
    int j = threadIdx.x;
    float dot = 0.f, ss = 0.f;
#pragma unroll
    for (int s = 0; s < SPLITS; ++s) {
        dot += g_pdot[s * M + j];
        ss  += g_pss [s * M + j];
    }
    float norm = fmaxf(sqrtf(ss), 1e-12f);
    float t = dot / norm;

    __shared__ float red[32];
    __shared__ float bcast;
    int lane = j & 31, wid = j >> 5;

    float m = t;
#pragma unroll
    for (int o = 16; o > 0; o >>= 1) m = fmaxf(m, __shfl_down_sync(0xFFFFFFFFu, m, o));
    if (lane == 0) red[wid] = m;
    __syncthreads();
    if (wid == 0) {
        float x = red[lane];
#pragma unroll
        for (int o = 16; o > 0; o >>= 1) x = fmaxf(x, __shfl_down_sync(0xFFFFFFFFu, x, o));
        if (lane == 0) bcast = x;
    }
    __syncthreads();
    float tmax = bcast;

    float e = expf(t - tmax);

    float su = warp_reduce_sum(e);
    __syncthreads();
    if (lane == 0) red[wid] = su;
    __syncthreads();
    if (wid == 0) {
        float x = red[lane];
        x = warp_reduce_sum(x);
        if (lane == 0) bcast = x;
    }
    __syncthreads();
    float esum = bcast;

    g_c[j] = e / (esum * norm);
}

// ---------------------------------------------------------------------------
// K4: u[d] = dot(mn[d,:], c) — warp-per-row, 8 float4/lane, L2-hot mn
// ---------------------------------------------------------------------------
__global__ __launch_bounds__(256) void k_u(const float* __restrict__ mn) {
    int warp = threadIdx.x >> 5, lane = threadIdx.x & 31;
    int row = blockIdx.x * 8 + warp;
    const float4* r  = reinterpret_cast<const float4*>(mn + (size_t)row * M);
    const float4* c4 = reinterpret_cast<const float4*>(g_c);
    float a0 = 0.f, a1 = 0.f, a2 = 0.f, a3 = 0.f;
#pragma unroll
    for (int k = 0; k < 8; k += 4) {
        int i0 = lane + (k + 0) * 32;
        int i1 = lane + (k + 1) * 32;
        int i2 = lane + (k + 2) * 32;
        int i3 = lane + (k + 3) * 32;
        float4 m0 = r[i0];
        float4 m1 = r[i1];
        float4 m2 = r[i2];
        float4 m3 = r[i3];
        a0 += dot4(m0, __ldg(&c4[i0]));
        a1 += dot4(m1, __ldg(&c4[i1]));
        a2 += dot4(m2, __ldg(&c4[i2]));
        a3 += dot4(m3, __ldg(&c4[i3]));
    }
    float acc = warp_reduce_sum((a0 + a1) + (a2 + a3));
    if (lane == 0) g_u[row] = acc;
}

// ---------------------------------------------------------------------------
// K5: v[d] = prelu(s_q[d] + dot(H[d,:], u), a_out) — warp-per-row, 32 f4/lane
// ---------------------------------------------------------------------------
__global__ __launch_bounds__(256) void k_v(const float* __restrict__ H,
                                           const float* __restrict__ a_out) {
    int warp = threadIdx.x >> 5, lane = threadIdx.x & 31;
    int row = blockIdx.x * 8 + warp;
    const float4* Hr = reinterpret_cast<const float4*>(H + (size_t)row * D);
    const float4* u4 = reinterpret_cast<const float4*>(g_u);
    float a0 = 0.f, a1 = 0.f, a2 = 0.f, a3 = 0.f;
#pragma unroll 4
    for (int k = 0; k < 32; k += 4) {
        int i0 = lane + (k + 0) * 32;
        int i1 = lane + (k + 1) * 32;
        int i2 = lane + (k + 2) * 32;
        int i3 = lane + (k + 3) * 32;
        float4 f0 = ldcs4(&Hr[i0]);
        float4 f1 = ldcs4(&Hr[i1]);
        float4 f2 = ldcs4(&Hr[i2]);
        float4 f3 = ldcs4(&Hr[i3]);
        a0 += dot4(f0, __ldg(&u4[i0]));
        a1 += dot4(f1, __ldg(&u4[i1]));
        a2 += dot4(f2, __ldg(&u4[i2]));
        a3 += dot4(f3, __ldg(&u4[i3]));
    }
    float acc = warp_reduce_sum((a0 + a1) + (a2 + a3));
    if (lane == 0) {
        float x = g_sq[row] + acc;
        float a = __ldg(a_out);
        g_v[row] = (x >= 0.f) ? x : a * x;
    }
}

// ---------------------------------------------------------------------------
// K6: y[d] = dot(R[d,:], v) — warp-per-row, 32 f4/lane -> d_out
// ---------------------------------------------------------------------------
__global__ __launch_bounds__(256) void k_y(const float* __restrict__ R,
                                           float* __restrict__ out) {
    int warp = threadIdx.x >> 5, lane = threadIdx.x & 31;
    int row = blockIdx.x * 8 + warp;
    const float4* Rr = reinterpret_cast<const float4*>(R + (size_t)row * D);
    const float4* v4 = reinterpret_cast<const float4*>(g_v);
    float a0 = 0.f, a1 = 0.f, a2 = 0.f, a3 = 0.f;
#pragma unroll 4
    for (int k = 0; k < 32; k += 4) {
        int i0 = lane + (k + 0) * 32;
        int i1 = lane + (k + 1) * 32;
        int i2 = lane + (k + 2) * 32;
        int i3 = lane + (k + 3) * 32;
        float4 f0 = ldcs4(&Rr[i0]);
        float4 f1 = ldcs4(&Rr[i1]);
        float4 f2 = ldcs4(&Rr[i2]);
        float4 f3 = ldcs4(&Rr[i3]);
        a0 += dot4(f0, __ldg(&v4[i0]));
        a1 += dot4(f1, __ldg(&v4[i1]));
        a2 += dot4(f2, __ldg(&v4[i2]));
        a3 += dot4(f3, __ldg(&v4[i3]));
    }
    float acc = warp_reduce_sum((a0 + a1) + (a2 + a3));
    if (lane == 0) out[row] = acc;
}

extern "C" void kernel_launch(void* const* d_in, const int* in_sizes, int n_in,
                              void* d_out, int out_size) {
    // metadata order: input, query, F_i, F_q, keys, memory_nodes, U, V, W, R, H, a_mem, a_out
    const float* query = (const float*)d_in[1];
    const float* F_q   = (const float*)d_in[3];
    const float* mn    = (const float*)d_in[5];
    const float* Rm    = (const float*)d_in[9];
    const float* Hm    = (const float*)d_in[10];
    const float* a_out = (const float*)d_in[12];
    float* out = (float*)d_out;

    k_sq<<<D / 8, 256>>>(F_q, query);
    dim3 g2(M / 256, SPLITS);
    k_colpart<<<g2, 256>>>(mn);
    k_softmax<<<1, 1024>>>();
    k_u<<<D / 8, 256>>>(mn);
    k_v<<<D / 8, 256>>>(Hm, a_out);
    k_y<<<D / 8, 256>>>(Rm, out);
}